// round 15
// baseline (speedup 1.0000x reference)
#include <cuda_runtime.h>
#include <cuda_fp16.h>
#include <math.h>
#include <stdint.h>

#define M_TOT 12608
#define D_DIM 768
#define H_DIM 3072
#define R_DIM 16

#define BM 128
#define BK 32
#define STAGES 4
#define ROWSTRIDE 40   // 32 fp16 + 8 pad

// ---------------------------------------------------------------------------
// Device-global scratch
// ---------------------------------------------------------------------------
__device__ __align__(16) __half g_x    [(size_t)M_TOT * D_DIM];
__device__ __align__(16) __half g_w1   [(size_t)H_DIM * D_DIM];
__device__ __align__(16) __half g_w2   [(size_t)D_DIM * H_DIM];
__device__ __align__(16) __half g_h    [(size_t)M_TOT * H_DIM];
__device__ __align__(16) __half g_tc   [(size_t)M_TOT * 32];    // [Thi|Tlo]
__device__ __align__(16) __half g_bc1  [(size_t)H_DIM * 32];    // [Bhi|Bhi]
__device__ __align__(16) __half g_bc2  [(size_t)D_DIM * 32];
__device__ __align__(16) __half g_a1h  [(size_t)R_DIM * D_DIM];
__device__ __align__(16) __half g_a2h  [(size_t)R_DIM * H_DIM];

// ---------------------------------------------------------------------------
// PTX helpers
// ---------------------------------------------------------------------------
__device__ __forceinline__ uint32_t smem_u32(const void* p) {
    uint32_t a;
    asm("{ .reg .u64 t; cvta.to.shared.u64 t, %1; cvt.u32.u64 %0, t; }" : "=r"(a) : "l"(p));
    return a;
}
#define CP_ASYNC16(dst, src) \
    asm volatile("cp.async.cg.shared.global [%0], [%1], 16;" :: "r"(dst), "l"(src))
#define CP_COMMIT() asm volatile("cp.async.commit_group;" ::: "memory")
#define CP_WAIT(n)  asm volatile("cp.async.wait_group %0;" :: "n"(n) : "memory")

#define LDSM4(r, addr) \
    asm volatile("ldmatrix.sync.aligned.m8n8.x4.shared.b16 {%0,%1,%2,%3}, [%4];" \
                 : "=r"((r)[0]), "=r"((r)[1]), "=r"((r)[2]), "=r"((r)[3]) : "r"(addr))

#define MMA16816H(d, a, b0, b1) \
    asm volatile("mma.sync.aligned.m16n8k16.row.col.f32.f16.f16.f32 " \
                 "{%0,%1,%2,%3}, {%4,%5,%6,%7}, {%8,%9}, {%0,%1,%2,%3};" \
                 : "+f"((d)[0]), "+f"((d)[1]), "+f"((d)[2]), "+f"((d)[3]) \
                 : "r"((a)[0]), "r"((a)[1]), "r"((a)[2]), "r"((a)[3]), \
                   "r"(b0), "r"(b1))

__device__ __forceinline__ uint32_t pack2h(float a, float b) {
    __half2 h = __floats2half2_rn(a, b);
    return *(uint32_t*)&h;
}

// ---------------------------------------------------------------------------
// prep_all: x/W1/W2/A1/A2 fp16 + bc1/bc2 (32-wide)
// ---------------------------------------------------------------------------
__global__ __launch_bounds__(256)
void prep_all_kernel(const float4* __restrict__ x, uint2* __restrict__ xh,
                     const float4* __restrict__ W1, uint2* __restrict__ w1h,
                     const float4* __restrict__ W2, uint2* __restrict__ w2h,
                     const float* __restrict__ B1f, __half* __restrict__ bc1,
                     const float* __restrict__ B2f, __half* __restrict__ bc2,
                     const float4* __restrict__ A1f, uint2* __restrict__ a1h,
                     const float4* __restrict__ A2f, uint2* __restrict__ a2h) {
    const int stride = gridDim.x * blockDim.x;
    const int tid0 = blockIdx.x * blockDim.x + threadIdx.x;
    const int nx4 = M_TOT * D_DIM / 4;
    const int nw4 = H_DIM * D_DIM / 4;
    const int na1 = R_DIM * D_DIM / 4;
    const int na2 = R_DIM * H_DIM / 4;
    for (int i = tid0; i < nx4; i += stride) {
        float4 v = x[i];
        uint2 u;
        u.x = pack2h(v.x, v.y);
        u.y = pack2h(v.z, v.w);
        xh[i] = u;
    }
    for (int i = tid0; i < nw4; i += stride) {
        float4 v = W1[i];
        uint2 u;
        u.x = pack2h(v.x, v.y);
        u.y = pack2h(v.z, v.w);
        w1h[i] = u;
    }
    for (int i = tid0; i < nw4; i += stride) {
        float4 v = W2[i];
        uint2 u;
        u.x = pack2h(v.x, v.y);
        u.y = pack2h(v.z, v.w);
        w2h[i] = u;
    }
    for (int i = tid0; i < na1; i += stride) {
        float4 v = A1f[i];
        uint2 u;
        u.x = pack2h(v.x, v.y);
        u.y = pack2h(v.z, v.w);
        a1h[i] = u;
    }
    for (int i = tid0; i < na2; i += stride) {
        float4 v = A2f[i];
        uint2 u;
        u.x = pack2h(v.x, v.y);
        u.y = pack2h(v.z, v.w);
        a2h[i] = u;
    }
    for (int n = tid0; n < H_DIM; n += stride) {
#pragma unroll
        for (int r = 0; r < 16; r++) {
            __half hi = __float2half_rn(B1f[n * 16 + r]);
            bc1[(size_t)n * 32 + r] = hi;
            bc1[(size_t)n * 32 + 16 + r] = hi;
        }
    }
    for (int n = tid0; n < D_DIM; n += stride) {
#pragma unroll
        for (int r = 0; r < 16; r++) {
            __half hi = __float2half_rn(B2f[n * 16 + r]);
            bc2[(size_t)n * 32 + r] = hi;
            bc2[(size_t)n * 32 + 16 + r] = hi;
        }
    }
}

// ---------------------------------------------------------------------------
// proj_mma: Tc[m][0..15]=hi, [16..31]=lo of In @ Ah^T, tensor cores.
// CTA 128 thr / 4 warps, 64 rows; 3-stage cp.async; BK=64 internal.
// ---------------------------------------------------------------------------
#define PRS 72   // proj rowstride (64 halves + 8)
__global__ __launch_bounds__(128)
void proj_mma_kernel(const __half* __restrict__ In, const __half* __restrict__ Ah,
                     __half* __restrict__ Tc, int Kd) {
    constexpr int A_BYTES = 64 * PRS * 2;
    constexpr int B_BYTES = 16 * PRS * 2;
    constexpr int STG = A_BYTES + B_BYTES;

    extern __shared__ char smem[];
    const uint32_t sb = smem_u32(smem);

    const int tid = threadIdx.x;
    const int lane = tid & 31;
    const int w = tid >> 5;
    const int m0 = blockIdx.x * 64;

    const uint32_t aoff = ((uint32_t)(w * 16 + (lane & 15)) * PRS + (lane >> 4) * 8) * 2;
    const uint32_t boff = ((uint32_t)(((lane >> 4) & 1) * 8 + (lane & 7)) * PRS +
                           ((lane >> 3) & 1) * 8) * 2;

    float acc[2][4] = {{0.f, 0.f, 0.f, 0.f}, {0.f, 0.f, 0.f, 0.f}};
    const int nchunks = Kd / 64;

    auto load_tile = [&](int stage, int c) {
        const uint32_t sA = sb + stage * STG;
        const uint32_t sB = sA + A_BYTES;
        const int kk = c * 64;
#pragma unroll
        for (int j = 0; j < 4; j++) {
            int u = j * 128 + tid;
            int row = u >> 3, grp = u & 7;
            CP_ASYNC16(sA + (uint32_t)(row * PRS + grp * 8) * 2,
                       In + (size_t)(m0 + row) * Kd + kk + grp * 8);
        }
        {
            int row = tid >> 3, grp = tid & 7;
            CP_ASYNC16(sB + (uint32_t)(row * PRS + grp * 8) * 2,
                       Ah + (size_t)row * Kd + kk + grp * 8);
        }
    };

    load_tile(0, 0);
    CP_COMMIT();
    if (nchunks > 1) load_tile(1, 1);
    CP_COMMIT();

    for (int t = 0; t < nchunks; t++) {
        CP_WAIT(1);
        __syncthreads();
        const uint32_t sA = sb + (t % 3) * STG;
        const uint32_t sB = sA + A_BYTES;
#pragma unroll
        for (int s4 = 0; s4 < 4; s4++) {
            uint32_t af[4], bf[4];
            LDSM4(af, sA + aoff + s4 * 32);
            LDSM4(bf, sB + boff + s4 * 32);
            MMA16816H(acc[0], af, bf[0], bf[1]);
            MMA16816H(acc[1], af, bf[2], bf[3]);
        }
        __syncthreads();
        if (t + 2 < nchunks) load_tile((t + 2) % 3, t + 2);
        CP_COMMIT();
    }

    const int rbase = m0 + w * 16 + (lane >> 2);
#pragma unroll
    for (int g = 0; g < 2; g++) {
        const int c = g * 8 + (lane & 3) * 2;
#pragma unroll
        for (int hh = 0; hh < 2; hh++) {
            const int gm = rbase + hh * 8;
            float v0 = acc[g][hh * 2 + 0];
            float v1 = acc[g][hh * 2 + 1];
            __half h0 = __float2half_rn(v0), h1 = __float2half_rn(v1);
            __half2 ph = __halves2half2(h0, h1);
            *(uint32_t*)(Tc + (size_t)gm * 32 + c) = *(uint32_t*)&ph;
            *(uint32_t*)(Tc + (size_t)gm * 32 + 16 + c) =
                pack2h(v0 - __half2float(h0), v1 - __half2float(h1));
        }
    }
}

// ---------------------------------------------------------------------------
// K-dim segments (fp16 pass + LoRA tail), BK=32 chunks
// ---------------------------------------------------------------------------
struct Segs {
    const __half* a[2];
    const __half* b[2];
    int sa[2];
    int sb[2];
    int nchunks[2];
};

// ---------------------------------------------------------------------------
// fp16 mma.sync GEMM. CTA 128x64, 256 thr, 8 warps (32x32), BK=32,
// 4 stages, 3 CTAs/SM.
// ---------------------------------------------------------------------------
template <int DO_GELU>
__global__ __launch_bounds__(256, 3)
void fc_mma_kernel(Segs segs, int total_chunks,
                   const float* __restrict__ bias,
                   __half* __restrict__ Ch, float* __restrict__ Cf, int Nld) {
    constexpr int BNT = 64;
    constexpr int NJ = 2;
    constexpr int A_BYTES = BM * ROWSTRIDE * 2;    // 10240
    constexpr int B_BYTES = BNT * ROWSTRIDE * 2;   // 5120
    constexpr int STG_BYTES = A_BYTES + B_BYTES;   // 15360

    extern __shared__ char smem[];
    const uint32_t smem_base = smem_u32(smem);

    const int tid = threadIdx.x;
    const int wid = tid >> 5;
    const int lane = tid & 31;
    const int wm = wid >> 1;   // 0..3 -> 32-row slab
    const int wn = wid & 1;    // 0..1 -> 32-col slab
    const int m0 = blockIdx.y * BM;
    const int n0 = blockIdx.x * BNT;

    int ls = 0, lc = 0;

    const uint32_t aoff = ((uint32_t)(wm * 32 + (lane & 15)) * ROWSTRIDE + (lane >> 4) * 8) * 2;
    const uint32_t boff = ((uint32_t)(wn * 32 + ((lane >> 4) & 1) * 8 + (lane & 7)) * ROWSTRIDE +
                           ((lane >> 3) & 1) * 8) * 2;

    float acc[2][4][4];
#pragma unroll
    for (int i = 0; i < 2; i++)
#pragma unroll
        for (int j = 0; j < 4; j++)
#pragma unroll
            for (int k = 0; k < 4; k++) acc[i][j][k] = 0.f;

    auto load_tile = [&](int stage) {
        const __half* Ap = segs.a[ls];
        const __half* Bp = segs.b[ls];
        const int stA = segs.sa[ls];
        const int stB = segs.sb[ls];
        const int kk = lc * BK;
        const uint32_t sA = smem_base + stage * STG_BYTES;
        const uint32_t sB = sA + A_BYTES;
        // A: 128 rows x 4 units = 512 / 256 thr = 2 iters
#pragma unroll
        for (int j = 0; j < 2; j++) {
            int u = j * 256 + tid;
            int row = u >> 2, grp = u & 3;
            int gm = m0 + row;
            if (gm >= M_TOT) gm = M_TOT - 1;
            CP_ASYNC16(sA + (uint32_t)(row * ROWSTRIDE + grp * 8) * 2,
                       Ap + (size_t)gm * stA + kk + grp * 8);
        }
        // B: 64 rows x 4 units = 256 = 1 iter
        {
            int row = tid >> 2, grp = tid & 3;
            CP_ASYNC16(sB + (uint32_t)(row * ROWSTRIDE + grp * 8) * 2,
                       Bp + (size_t)(n0 + row) * stB + kk + grp * 8);
        }
        if (++lc == segs.nchunks[ls]) { lc = 0; ++ls; }
    };

#pragma unroll
    for (int s = 0; s < STAGES - 1; s++) {
        load_tile(s);
        CP_COMMIT();
    }

    for (int t = 0; t < total_chunks; t++) {
        CP_WAIT(STAGES - 2);
        __syncthreads();

        const uint32_t sA = smem_base + (t % STAGES) * STG_BYTES;
        const uint32_t sB = sA + A_BYTES;

        uint32_t af[2][2][4];
#pragma unroll
        for (int mi = 0; mi < 2; mi++)
#pragma unroll
            for (int k = 0; k < 2; k++)
                LDSM4(af[mi][k], sA + aoff + (uint32_t)(mi * 16 * ROWSTRIDE + k * 16) * 2);

#pragma unroll
        for (int nj = 0; nj < NJ; nj++) {
            uint32_t bf[2][4];
#pragma unroll
            for (int k = 0; k < 2; k++)
                LDSM4(bf[k], sB + boff + (uint32_t)(nj * 16 * ROWSTRIDE + k * 16) * 2);
#pragma unroll
            for (int mi = 0; mi < 2; mi++)
#pragma unroll
                for (int h = 0; h < 2; h++) {
                    MMA16816H(acc[mi][nj * 2 + h], af[mi][0], bf[0][h * 2], bf[0][h * 2 + 1]);
                    MMA16816H(acc[mi][nj * 2 + h], af[mi][1], bf[1][h * 2], bf[1][h * 2 + 1]);
                }
        }

        if (t + STAGES - 1 < total_chunks) load_tile((t + STAGES - 1) % STAGES);
        CP_COMMIT();
    }

    // ---- epilogue ----
#pragma unroll
    for (int mi = 0; mi < 2; mi++) {
        const int rbase = m0 + wm * 32 + mi * 16 + (lane >> 2);
#pragma unroll
        for (int ni = 0; ni < 4; ni++) {
            const int gn = n0 + wn * 32 + ni * 8 + (lane & 3) * 2;
            const float b0 = __ldg(bias + gn);
            const float b1 = __ldg(bias + gn + 1);
#pragma unroll
            for (int h = 0; h < 2; h++) {
                const int gm = rbase + h * 8;
                if (gm >= M_TOT) continue;
                float v0 = acc[mi][ni][h * 2 + 0] + b0;
                float v1 = acc[mi][ni][h * 2 + 1] + b1;
                if (DO_GELU) {
                    v0 = 0.5f * v0 * (1.0f + erff(v0 * 0.70710678118654752f));
                    v1 = 0.5f * v1 * (1.0f + erff(v1 * 0.70710678118654752f));
                    *(uint32_t*)(Ch + (size_t)gm * Nld + gn) = pack2h(v0, v1);
                } else {
                    *(float2*)(Cf + (size_t)gm * Nld + gn) = make_float2(v0, v1);
                }
            }
        }
    }
}

// ---------------------------------------------------------------------------
// Launch sequence
// ---------------------------------------------------------------------------
extern "C" void kernel_launch(void* const* d_in, const int* in_sizes, int n_in,
                              void* d_out, int out_size) {
    const float* x  = (const float*)d_in[0];
    const float* W1 = (const float*)d_in[1];
    const float* b1 = (const float*)d_in[2];
    const float* A1 = (const float*)d_in[3];
    const float* B1 = (const float*)d_in[4];
    const float* W2 = (const float*)d_in[5];
    const float* b2 = (const float*)d_in[6];
    const float* A2 = (const float*)d_in[7];
    const float* B2 = (const float*)d_in[8];
    float* out = (float*)d_out;

    __half *xh, *w1h, *w2h, *hh, *tc, *bc1, *bc2, *a1h, *a2h;
    cudaGetSymbolAddress((void**)&xh,  g_x);
    cudaGetSymbolAddress((void**)&w1h, g_w1);
    cudaGetSymbolAddress((void**)&w2h, g_w2);
    cudaGetSymbolAddress((void**)&hh,  g_h);
    cudaGetSymbolAddress((void**)&tc,  g_tc);
    cudaGetSymbolAddress((void**)&bc1, g_bc1);
    cudaGetSymbolAddress((void**)&bc2, g_bc2);
    cudaGetSymbolAddress((void**)&a1h, g_a1h);
    cudaGetSymbolAddress((void**)&a2h, g_a2h);

    constexpr int SMF = STAGES * (BM + 64) * ROWSTRIDE * 2;              // 61440
    constexpr int SMP = 3 * (64 * PRS * 2 + 16 * PRS * 2);               // 34560
    cudaFuncSetAttribute((const void*)fc_mma_kernel<1>,
                         cudaFuncAttributeMaxDynamicSharedMemorySize, SMF);
    cudaFuncSetAttribute((const void*)fc_mma_kernel<0>,
                         cudaFuncAttributeMaxDynamicSharedMemorySize, SMF);
    cudaFuncSetAttribute((const void*)proj_mma_kernel,
                         cudaFuncAttributeMaxDynamicSharedMemorySize, SMP);

    prep_all_kernel<<<592, 256>>>(
        (const float4*)x, (uint2*)xh,
        (const float4*)W1, (uint2*)w1h,
        (const float4*)W2, (uint2*)w2h,
        B1, bc1, B2, bc2,
        (const float4*)A1, (uint2*)a1h,
        (const float4*)A2, (uint2*)a2h);

    proj_mma_kernel<<<M_TOT / 64, 128, SMP>>>(xh, a1h, tc, D_DIM);

    {
        Segs s;
        s.a[0] = xh; s.b[0] = w1h; s.sa[0] = D_DIM; s.sb[0] = D_DIM; s.nchunks[0] = D_DIM / BK;
        s.a[1] = tc; s.b[1] = bc1; s.sa[1] = 32;    s.sb[1] = 32;    s.nchunks[1] = 1;
        int total = D_DIM / BK + 1;  // 25
        dim3 grid(H_DIM / 64, (M_TOT + BM - 1) / BM);
        fc_mma_kernel<1><<<grid, 256, SMF>>>(s, total, b1, hh, nullptr, H_DIM);
    }

    proj_mma_kernel<<<M_TOT / 64, 128, SMP>>>(hh, a2h, tc, H_DIM);

    {
        Segs s;
        s.a[0] = hh; s.b[0] = w2h; s.sa[0] = H_DIM; s.sb[0] = H_DIM; s.nchunks[0] = H_DIM / BK;
        s.a[1] = tc; s.b[1] = bc2; s.sa[1] = 32;    s.sb[1] = 32;    s.nchunks[1] = 1;
        int total = H_DIM / BK + 1;  // 97
        dim3 grid(D_DIM / 64, (M_TOT + BM - 1) / BM);
        fc_mma_kernel<0><<<grid, 256, SMF>>>(s, total, b2, nullptr, out, D_DIM);
    }
}

// round 16
// speedup vs baseline: 1.1587x; 1.1587x over previous
#include <cuda_runtime.h>
#include <cuda_fp16.h>
#include <math.h>
#include <stdint.h>

#define M_TOT 12608
#define D_DIM 768
#define H_DIM 3072
#define R_DIM 16

#define BM 128
#define BK 64
#define STAGES 3
#define ROWSTRIDE 72   // 64 fp16 + 8 pad

// ---------------------------------------------------------------------------
// Device-global scratch
// ---------------------------------------------------------------------------
__device__ __align__(16) __half g_x    [(size_t)M_TOT * D_DIM];
__device__ __align__(16) __half g_w1   [(size_t)H_DIM * D_DIM];
__device__ __align__(16) __half g_w2   [(size_t)D_DIM * H_DIM];
__device__ __align__(16) __half g_h    [(size_t)M_TOT * H_DIM];
__device__ __align__(16) __half g_tc   [(size_t)M_TOT * 64];   // [Thi|Tlo|0|0]
__device__ __align__(16) __half g_bc1  [(size_t)H_DIM * 64];   // [Bhi|Bhi|0|0]
__device__ __align__(16) __half g_bc2  [(size_t)D_DIM * 64];
__device__ __align__(16) __half g_a1h  [(size_t)R_DIM * D_DIM]; // A1 fp16 [16][768]
__device__ __align__(16) __half g_a2h  [(size_t)R_DIM * H_DIM]; // A2 fp16 [16][3072]

// ---------------------------------------------------------------------------
// PTX helpers
// ---------------------------------------------------------------------------
__device__ __forceinline__ uint32_t smem_u32(const void* p) {
    uint32_t a;
    asm("{ .reg .u64 t; cvta.to.shared.u64 t, %1; cvt.u32.u64 %0, t; }" : "=r"(a) : "l"(p));
    return a;
}
#define CP_ASYNC16(dst, src) \
    asm volatile("cp.async.cg.shared.global [%0], [%1], 16;" :: "r"(dst), "l"(src))
#define CP_COMMIT() asm volatile("cp.async.commit_group;" ::: "memory")
#define CP_WAIT(n)  asm volatile("cp.async.wait_group %0;" :: "n"(n) : "memory")

#define LDSM4(r, addr) \
    asm volatile("ldmatrix.sync.aligned.m8n8.x4.shared.b16 {%0,%1,%2,%3}, [%4];" \
                 : "=r"((r)[0]), "=r"((r)[1]), "=r"((r)[2]), "=r"((r)[3]) : "r"(addr))

#define MMA16816H(d, a, b0, b1) \
    asm volatile("mma.sync.aligned.m16n8k16.row.col.f32.f16.f16.f32 " \
                 "{%0,%1,%2,%3}, {%4,%5,%6,%7}, {%8,%9}, {%0,%1,%2,%3};" \
                 : "+f"((d)[0]), "+f"((d)[1]), "+f"((d)[2]), "+f"((d)[3]) \
                 : "r"((a)[0]), "r"((a)[1]), "r"((a)[2]), "r"((a)[3]), \
                   "r"(b0), "r"(b1))

__device__ __forceinline__ uint32_t pack2h(float a, float b) {
    __half2 h = __floats2half2_rn(a, b);
    return *(uint32_t*)&h;
}

// ---------------------------------------------------------------------------
// prep_all: x/W1/W2/A1/A2 fp16, bc1/bc2 (64-wide), Tc upper-zero
// ---------------------------------------------------------------------------
__global__ __launch_bounds__(256)
void prep_all_kernel(const float4* __restrict__ x, uint2* __restrict__ xh,
                     const float4* __restrict__ W1, uint2* __restrict__ w1h,
                     const float4* __restrict__ W2, uint2* __restrict__ w2h,
                     const float* __restrict__ B1f, __half* __restrict__ bc1,
                     const float* __restrict__ B2f, __half* __restrict__ bc2,
                     const float4* __restrict__ A1f, uint2* __restrict__ a1h,
                     const float4* __restrict__ A2f, uint2* __restrict__ a2h,
                     __half* __restrict__ tc) {
    const int stride = gridDim.x * blockDim.x;
    const int tid0 = blockIdx.x * blockDim.x + threadIdx.x;
    const int nx4 = M_TOT * D_DIM / 4;
    const int nw4 = H_DIM * D_DIM / 4;
    const int na1 = R_DIM * D_DIM / 4;
    const int na2 = R_DIM * H_DIM / 4;
    for (int i = tid0; i < nx4; i += stride) {
        float4 v = x[i];
        uint2 u;
        u.x = pack2h(v.x, v.y);
        u.y = pack2h(v.z, v.w);
        xh[i] = u;
    }
    for (int i = tid0; i < nw4; i += stride) {
        float4 v = W1[i];
        uint2 u;
        u.x = pack2h(v.x, v.y);
        u.y = pack2h(v.z, v.w);
        w1h[i] = u;
    }
    for (int i = tid0; i < nw4; i += stride) {
        float4 v = W2[i];
        uint2 u;
        u.x = pack2h(v.x, v.y);
        u.y = pack2h(v.z, v.w);
        w2h[i] = u;
    }
    for (int i = tid0; i < na1; i += stride) {
        float4 v = A1f[i];
        uint2 u;
        u.x = pack2h(v.x, v.y);
        u.y = pack2h(v.z, v.w);
        a1h[i] = u;
    }
    for (int i = tid0; i < na2; i += stride) {
        float4 v = A2f[i];
        uint2 u;
        u.x = pack2h(v.x, v.y);
        u.y = pack2h(v.z, v.w);
        a2h[i] = u;
    }
    const __half hz = __float2half_rn(0.f);
    for (int n = tid0; n < H_DIM; n += stride) {
#pragma unroll
        for (int r = 0; r < 16; r++) {
            __half hi = __float2half_rn(B1f[n * 16 + r]);
            bc1[(size_t)n * 64 + r] = hi;
            bc1[(size_t)n * 64 + 16 + r] = hi;
            bc1[(size_t)n * 64 + 32 + r] = hz;
            bc1[(size_t)n * 64 + 48 + r] = hz;
        }
    }
    for (int n = tid0; n < D_DIM; n += stride) {
#pragma unroll
        for (int r = 0; r < 16; r++) {
            __half hi = __float2half_rn(B2f[n * 16 + r]);
            bc2[(size_t)n * 64 + r] = hi;
            bc2[(size_t)n * 64 + 16 + r] = hi;
            bc2[(size_t)n * 64 + 32 + r] = hz;
            bc2[(size_t)n * 64 + 48 + r] = hz;
        }
    }
    // zero Tc cols 32..63 (proj_mma writes only cols 0..31)
    for (int m = tid0; m < M_TOT; m += stride) {
        uint4* d = (uint4*)(tc + (size_t)m * 64 + 32);
        d[0] = make_uint4(0, 0, 0, 0);
        d[1] = make_uint4(0, 0, 0, 0);
        d[2] = make_uint4(0, 0, 0, 0);
        d[3] = make_uint4(0, 0, 0, 0);
    }
}

// ---------------------------------------------------------------------------
// proj_mma: Tc[m][0..15]=hi, [16..31]=lo of In[m,:] @ Ah[16,:]^T via tensor
// cores. CTA: 128 thr / 4 warps, 64 rows; warp tile 16x16; 3-stage cp.async.
// ---------------------------------------------------------------------------
__global__ __launch_bounds__(128)
void proj_mma_kernel(const __half* __restrict__ In, const __half* __restrict__ Ah,
                     __half* __restrict__ Tc, int Kd) {
    constexpr int A_BYTES = 64 * ROWSTRIDE * 2;   // 9216
    constexpr int B_BYTES = 16 * ROWSTRIDE * 2;   // 2304
    constexpr int STG = A_BYTES + B_BYTES;

    extern __shared__ char smem[];
    const uint32_t sb = smem_u32(smem);

    const int tid = threadIdx.x;
    const int lane = tid & 31;
    const int w = tid >> 5;
    const int m0 = blockIdx.x * 64;

    const uint32_t aoff = ((uint32_t)(w * 16 + (lane & 15)) * ROWSTRIDE + (lane >> 4) * 8) * 2;
    const uint32_t boff = ((uint32_t)(((lane >> 4) & 1) * 8 + (lane & 7)) * ROWSTRIDE +
                           ((lane >> 3) & 1) * 8) * 2;

    float acc[2][4] = {{0.f, 0.f, 0.f, 0.f}, {0.f, 0.f, 0.f, 0.f}};

    const int nchunks = Kd / BK;

    auto load_tile = [&](int stage, int c) {
        const uint32_t sA = sb + stage * STG;
        const uint32_t sB = sA + A_BYTES;
        const int kk = c * BK;
#pragma unroll
        for (int j = 0; j < 4; j++) {
            int u = j * 128 + tid;
            int row = u >> 3, grp = u & 7;
            CP_ASYNC16(sA + (uint32_t)(row * ROWSTRIDE + grp * 8) * 2,
                       In + (size_t)(m0 + row) * Kd + kk + grp * 8);
        }
        {
            int row = tid >> 3, grp = tid & 7;
            CP_ASYNC16(sB + (uint32_t)(row * ROWSTRIDE + grp * 8) * 2,
                       Ah + (size_t)row * Kd + kk + grp * 8);
        }
    };

    load_tile(0, 0);
    CP_COMMIT();
    if (nchunks > 1) load_tile(1, 1);
    CP_COMMIT();

    for (int t = 0; t < nchunks; t++) {
        CP_WAIT(1);
        __syncthreads();
        // issue next tile's loads BEFORE compute
        if (t + 2 < nchunks) load_tile((t + 2) % 3, t + 2);
        CP_COMMIT();

        const uint32_t sA = sb + (t % 3) * STG;
        const uint32_t sB = sA + A_BYTES;
#pragma unroll
        for (int s4 = 0; s4 < 4; s4++) {
            uint32_t af[4], bf[4];
            LDSM4(af, sA + aoff + s4 * 32);
            LDSM4(bf, sB + boff + s4 * 32);
            MMA16816H(acc[0], af, bf[0], bf[1]);
            MMA16816H(acc[1], af, bf[2], bf[3]);
        }
        __syncthreads();
    }

    // epilogue: warp covers rows m0+w*16..+16, cols 0..15
    const int rbase = m0 + w * 16 + (lane >> 2);
#pragma unroll
    for (int g = 0; g < 2; g++) {
        const int c = g * 8 + (lane & 3) * 2;
#pragma unroll
        for (int hh = 0; hh < 2; hh++) {
            const int gm = rbase + hh * 8;
            float v0 = acc[g][hh * 2 + 0];
            float v1 = acc[g][hh * 2 + 1];
            __half h0 = __float2half_rn(v0), h1 = __float2half_rn(v1);
            __half2 ph = __halves2half2(h0, h1);
            *(uint32_t*)(Tc + (size_t)gm * 64 + c) = *(uint32_t*)&ph;
            *(uint32_t*)(Tc + (size_t)gm * 64 + 16 + c) =
                pack2h(v0 - __half2float(h0), v1 - __half2float(h1));
        }
    }
}

// ---------------------------------------------------------------------------
// K-dim segments (single fp16 pass + LoRA tail)
// ---------------------------------------------------------------------------
struct Segs {
    const __half* a[2];
    const __half* b[2];
    int sa[2];
    int sb[2];
    int nchunks[2];
};

// ---------------------------------------------------------------------------
// fp16 mma.sync GEMM (R14 config; loads issued before MMAs each iteration).
// ---------------------------------------------------------------------------
template <int DO_GELU, int BNT>
__global__ __launch_bounds__(256, 2)
void fc_mma_kernel(Segs segs, int total_chunks,
                   const float* __restrict__ bias,
                   __half* __restrict__ Ch, float* __restrict__ Cf, int Nld) {
    constexpr int NJ = BNT / 32;
    constexpr int A_BYTES = BM * ROWSTRIDE * 2;
    constexpr int B_BYTES = BNT * ROWSTRIDE * 2;
    constexpr int STG_BYTES = A_BYTES + B_BYTES;

    extern __shared__ char smem[];
    const uint32_t smem_base = smem_u32(smem);

    const int tid = threadIdx.x;
    const int wid = tid >> 5;
    const int lane = tid & 31;
    const int wm = wid >> 1;
    const int wn = wid & 1;
    const int m0 = blockIdx.y * BM;
    const int n0 = blockIdx.x * BNT;

    int ls = 0, lc = 0;

    const uint32_t aoff = ((uint32_t)(wm * 32 + (lane & 15)) * ROWSTRIDE + (lane >> 4) * 8) * 2;
    const uint32_t boff = ((uint32_t)(wn * (BNT / 2) + ((lane >> 4) & 1) * 8 + (lane & 7)) * ROWSTRIDE +
                           ((lane >> 3) & 1) * 8) * 2;

    float acc[2][NJ * 2][4];
#pragma unroll
    for (int i = 0; i < 2; i++)
#pragma unroll
        for (int j = 0; j < NJ * 2; j++)
#pragma unroll
            for (int k = 0; k < 4; k++) acc[i][j][k] = 0.f;

    auto load_tile = [&](int stage) {
        const __half* Ap = segs.a[ls];
        const __half* Bp = segs.b[ls];
        const int stA = segs.sa[ls];
        const int stB = segs.sb[ls];
        const int kk = lc * BK;
        const uint32_t sA = smem_base + stage * STG_BYTES;
        const uint32_t sB = sA + A_BYTES;
#pragma unroll
        for (int j = 0; j < 4; j++) {
            int u = j * 256 + tid;
            int row = u >> 3, grp = u & 7;
            int gm = m0 + row;
            if (gm >= M_TOT) gm = M_TOT - 1;
            CP_ASYNC16(sA + (uint32_t)(row * ROWSTRIDE + grp * 8) * 2,
                       Ap + (size_t)gm * stA + kk + grp * 8);
        }
#pragma unroll
        for (int j = 0; j < BNT / 32; j++) {
            int u = j * 256 + tid;
            int row = u >> 3, grp = u & 7;
            CP_ASYNC16(sB + (uint32_t)(row * ROWSTRIDE + grp * 8) * 2,
                       Bp + (size_t)(n0 + row) * stB + kk + grp * 8);
        }
        if (++lc == segs.nchunks[ls]) { lc = 0; ++ls; }
    };

#pragma unroll
    for (int s = 0; s < STAGES - 1; s++) {
        load_tile(s);
        CP_COMMIT();
    }

    for (int t = 0; t < total_chunks; t++) {
        CP_WAIT(STAGES - 2);
        __syncthreads();

        // issue next tile's loads BEFORE compute: LSU fills while tensor
        // cores run, and the loads get a full extra compute phase of slack.
        if (t + STAGES - 1 < total_chunks) load_tile((t + STAGES - 1) % STAGES);
        CP_COMMIT();

        const uint32_t sA = smem_base + (t % STAGES) * STG_BYTES;
        const uint32_t sB = sA + A_BYTES;

#pragma unroll
        for (int sub = 0; sub < 2; sub++) {
            const uint32_t ksub = (uint32_t)(sub * 32) * 2;
            uint32_t af[2][2][4];
#pragma unroll
            for (int mi = 0; mi < 2; mi++)
#pragma unroll
                for (int k = 0; k < 2; k++)
                    LDSM4(af[mi][k], sA + aoff + ksub + (uint32_t)(mi * 16 * ROWSTRIDE + k * 16) * 2);

#pragma unroll
            for (int nj = 0; nj < NJ; nj++) {
                uint32_t bf[2][4];
#pragma unroll
                for (int k = 0; k < 2; k++)
                    LDSM4(bf[k], sB + boff + ksub + (uint32_t)(nj * 16 * ROWSTRIDE + k * 16) * 2);
#pragma unroll
                for (int mi = 0; mi < 2; mi++)
#pragma unroll
                    for (int h = 0; h < 2; h++) {
                        MMA16816H(acc[mi][nj * 2 + h], af[mi][0], bf[0][h * 2], bf[0][h * 2 + 1]);
                        MMA16816H(acc[mi][nj * 2 + h], af[mi][1], bf[1][h * 2], bf[1][h * 2 + 1]);
                    }
            }
        }
        __syncthreads();
    }

    // ---- epilogue ----
#pragma unroll
    for (int mi = 0; mi < 2; mi++) {
        const int rbase = m0 + wm * 32 + mi * 16 + (lane >> 2);
#pragma unroll
        for (int ni = 0; ni < NJ * 2; ni++) {
            const int gn = n0 + wn * (BNT / 2) + ni * 8 + (lane & 3) * 2;
            const float b0 = __ldg(bias + gn);
            const float b1 = __ldg(bias + gn + 1);
#pragma unroll
            for (int h = 0; h < 2; h++) {
                const int gm = rbase + h * 8;
                if (gm >= M_TOT) continue;
                float v0 = acc[mi][ni][h * 2 + 0] + b0;
                float v1 = acc[mi][ni][h * 2 + 1] + b1;
                if (DO_GELU) {
                    v0 = 0.5f * v0 * (1.0f + erff(v0 * 0.70710678118654752f));
                    v1 = 0.5f * v1 * (1.0f + erff(v1 * 0.70710678118654752f));
                    *(uint32_t*)(Ch + (size_t)gm * Nld + gn) = pack2h(v0, v1);
                } else {
                    *(float2*)(Cf + (size_t)gm * Nld + gn) = make_float2(v0, v1);
                }
            }
        }
    }
}

// ---------------------------------------------------------------------------
// Launch sequence
// ---------------------------------------------------------------------------
extern "C" void kernel_launch(void* const* d_in, const int* in_sizes, int n_in,
                              void* d_out, int out_size) {
    const float* x  = (const float*)d_in[0];
    const float* W1 = (const float*)d_in[1];
    const float* b1 = (const float*)d_in[2];
    const float* A1 = (const float*)d_in[3];
    const float* B1 = (const float*)d_in[4];
    const float* W2 = (const float*)d_in[5];
    const float* b2 = (const float*)d_in[6];
    const float* A2 = (const float*)d_in[7];
    const float* B2 = (const float*)d_in[8];
    float* out = (float*)d_out;

    __half *xh, *w1h, *w2h, *hh, *tc, *bc1, *bc2, *a1h, *a2h;
    cudaGetSymbolAddress((void**)&xh,  g_x);
    cudaGetSymbolAddress((void**)&w1h, g_w1);
    cudaGetSymbolAddress((void**)&w2h, g_w2);
    cudaGetSymbolAddress((void**)&hh,  g_h);
    cudaGetSymbolAddress((void**)&tc,  g_tc);
    cudaGetSymbolAddress((void**)&bc1, g_bc1);
    cudaGetSymbolAddress((void**)&bc2, g_bc2);
    cudaGetSymbolAddress((void**)&a1h, g_a1h);
    cudaGetSymbolAddress((void**)&a2h, g_a2h);

    constexpr int SM1 = STAGES * (BM * ROWSTRIDE * 2 + 128 * ROWSTRIDE * 2);
    constexpr int SM2 = STAGES * (BM * ROWSTRIDE * 2 + 64 * ROWSTRIDE * 2);
    constexpr int SMP = 3 * (64 * ROWSTRIDE * 2 + 16 * ROWSTRIDE * 2);   // 34560
    cudaFuncSetAttribute((const void*)fc_mma_kernel<1, 128>,
                         cudaFuncAttributeMaxDynamicSharedMemorySize, SM1);
    cudaFuncSetAttribute((const void*)fc_mma_kernel<0, 64>,
                         cudaFuncAttributeMaxDynamicSharedMemorySize, SM2);
    cudaFuncSetAttribute((const void*)proj_mma_kernel,
                         cudaFuncAttributeMaxDynamicSharedMemorySize, SMP);

    prep_all_kernel<<<592, 256>>>(
        (const float4*)x, (uint2*)xh,
        (const float4*)W1, (uint2*)w1h,
        (const float4*)W2, (uint2*)w2h,
        B1, bc1, B2, bc2,
        (const float4*)A1, (uint2*)a1h,
        (const float4*)A2, (uint2*)a2h, tc);

    proj_mma_kernel<<<M_TOT / 64, 128, SMP>>>(xh, a1h, tc, D_DIM);

    {
        Segs s;
        s.a[0] = xh; s.b[0] = w1h; s.sa[0] = D_DIM; s.sb[0] = D_DIM; s.nchunks[0] = D_DIM / BK;
        s.a[1] = tc; s.b[1] = bc1; s.sa[1] = 64;    s.sb[1] = 64;    s.nchunks[1] = 1;
        int total = D_DIM / BK + 1;  // 13
        dim3 grid(H_DIM / 128, (M_TOT + BM - 1) / BM);
        fc_mma_kernel<1, 128><<<grid, 256, SM1>>>(s, total, b1, hh, nullptr, H_DIM);
    }

    proj_mma_kernel<<<M_TOT / 64, 128, SMP>>>(hh, a2h, tc, H_DIM);

    {
        Segs s;
        s.a[0] = hh; s.b[0] = w2h; s.sa[0] = H_DIM; s.sb[0] = H_DIM; s.nchunks[0] = H_DIM / BK;
        s.a[1] = tc; s.b[1] = bc2; s.sa[1] = 64;    s.sb[1] = 64;    s.nchunks[1] = 1;
        int total = H_DIM / BK + 1;  // 49
        dim3 grid(D_DIM / 64, (M_TOT + BM - 1) / BM);
        fc_mma_kernel<0, 64><<<grid, 256, SM2>>>(s, total, b2, nullptr, out, D_DIM);
    }
}

// round 17
// speedup vs baseline: 1.2075x; 1.0422x over previous
#include <cuda_runtime.h>
#include <cuda_fp16.h>
#include <math.h>
#include <stdint.h>

#define M_TOT 12608
#define D_DIM 768
#define H_DIM 3072
#define R_DIM 16

#define BM 128
#define BK 64
#define STAGES 3
#define ROWSTRIDE 72   // 64 fp16 + 8 pad

// ---------------------------------------------------------------------------
// Device-global scratch
// ---------------------------------------------------------------------------
__device__ __align__(16) __half g_x    [(size_t)M_TOT * D_DIM];
__device__ __align__(16) __half g_w1   [(size_t)H_DIM * D_DIM];
__device__ __align__(16) __half g_w2   [(size_t)D_DIM * H_DIM];
__device__ __align__(16) __half g_h    [(size_t)M_TOT * H_DIM];
__device__ __align__(16) __half g_tc   [(size_t)M_TOT * 64];   // [Thi|Tlo|0|0]
__device__ __align__(16) __half g_bc1  [(size_t)H_DIM * 64];   // [Bhi|Bhi|0|0]
__device__ __align__(16) __half g_bc2  [(size_t)D_DIM * 64];
__device__ __align__(16) __half g_a1h  [(size_t)R_DIM * D_DIM]; // A1 fp16 [16][768]
__device__ __align__(16) __half g_a2h  [(size_t)R_DIM * H_DIM]; // A2 fp16 [16][3072]

// ---------------------------------------------------------------------------
// PTX helpers
// ---------------------------------------------------------------------------
__device__ __forceinline__ uint32_t smem_u32(const void* p) {
    uint32_t a;
    asm("{ .reg .u64 t; cvta.to.shared.u64 t, %1; cvt.u32.u64 %0, t; }" : "=r"(a) : "l"(p));
    return a;
}
#define CP_ASYNC16(dst, src) \
    asm volatile("cp.async.cg.shared.global [%0], [%1], 16;" :: "r"(dst), "l"(src))
#define CP_COMMIT() asm volatile("cp.async.commit_group;" ::: "memory")
#define CP_WAIT(n)  asm volatile("cp.async.wait_group %0;" :: "n"(n) : "memory")

#define LDSM4(r, addr) \
    asm volatile("ldmatrix.sync.aligned.m8n8.x4.shared.b16 {%0,%1,%2,%3}, [%4];" \
                 : "=r"((r)[0]), "=r"((r)[1]), "=r"((r)[2]), "=r"((r)[3]) : "r"(addr))

#define MMA16816H(d, a, b0, b1) \
    asm volatile("mma.sync.aligned.m16n8k16.row.col.f32.f16.f16.f32 " \
                 "{%0,%1,%2,%3}, {%4,%5,%6,%7}, {%8,%9}, {%0,%1,%2,%3};" \
                 : "+f"((d)[0]), "+f"((d)[1]), "+f"((d)[2]), "+f"((d)[3]) \
                 : "r"((a)[0]), "r"((a)[1]), "r"((a)[2]), "r"((a)[3]), \
                   "r"(b0), "r"(b1))

__device__ __forceinline__ uint32_t pack2h(float a, float b) {
    __half2 h = __floats2half2_rn(a, b);
    return *(uint32_t*)&h;
}

// ---------------------------------------------------------------------------
// prep_all: x/W1/W2/A1/A2 fp16, bc1/bc2 (64-wide), Tc upper-zero
// ---------------------------------------------------------------------------
__global__ __launch_bounds__(256)
void prep_all_kernel(const float4* __restrict__ x, uint2* __restrict__ xh,
                     const float4* __restrict__ W1, uint2* __restrict__ w1h,
                     const float4* __restrict__ W2, uint2* __restrict__ w2h,
                     const float* __restrict__ B1f, __half* __restrict__ bc1,
                     const float* __restrict__ B2f, __half* __restrict__ bc2,
                     const float4* __restrict__ A1f, uint2* __restrict__ a1h,
                     const float4* __restrict__ A2f, uint2* __restrict__ a2h,
                     __half* __restrict__ tc) {
    const int stride = gridDim.x * blockDim.x;
    const int tid0 = blockIdx.x * blockDim.x + threadIdx.x;
    const int nx4 = M_TOT * D_DIM / 4;
    const int nw4 = H_DIM * D_DIM / 4;
    const int na1 = R_DIM * D_DIM / 4;
    const int na2 = R_DIM * H_DIM / 4;
    for (int i = tid0; i < nx4; i += stride) {
        float4 v = x[i];
        uint2 u;
        u.x = pack2h(v.x, v.y);
        u.y = pack2h(v.z, v.w);
        xh[i] = u;
    }
    for (int i = tid0; i < nw4; i += stride) {
        float4 v = W1[i];
        uint2 u;
        u.x = pack2h(v.x, v.y);
        u.y = pack2h(v.z, v.w);
        w1h[i] = u;
    }
    for (int i = tid0; i < nw4; i += stride) {
        float4 v = W2[i];
        uint2 u;
        u.x = pack2h(v.x, v.y);
        u.y = pack2h(v.z, v.w);
        w2h[i] = u;
    }
    for (int i = tid0; i < na1; i += stride) {
        float4 v = A1f[i];
        uint2 u;
        u.x = pack2h(v.x, v.y);
        u.y = pack2h(v.z, v.w);
        a1h[i] = u;
    }
    for (int i = tid0; i < na2; i += stride) {
        float4 v = A2f[i];
        uint2 u;
        u.x = pack2h(v.x, v.y);
        u.y = pack2h(v.z, v.w);
        a2h[i] = u;
    }
    const __half hz = __float2half_rn(0.f);
    for (int n = tid0; n < H_DIM; n += stride) {
#pragma unroll
        for (int r = 0; r < 16; r++) {
            __half hi = __float2half_rn(B1f[n * 16 + r]);
            bc1[(size_t)n * 64 + r] = hi;
            bc1[(size_t)n * 64 + 16 + r] = hi;
            bc1[(size_t)n * 64 + 32 + r] = hz;
            bc1[(size_t)n * 64 + 48 + r] = hz;
        }
    }
    for (int n = tid0; n < D_DIM; n += stride) {
#pragma unroll
        for (int r = 0; r < 16; r++) {
            __half hi = __float2half_rn(B2f[n * 16 + r]);
            bc2[(size_t)n * 64 + r] = hi;
            bc2[(size_t)n * 64 + 16 + r] = hi;
            bc2[(size_t)n * 64 + 32 + r] = hz;
            bc2[(size_t)n * 64 + 48 + r] = hz;
        }
    }
    // zero Tc cols 32..63 (proj_mma writes only cols 0..31)
    for (int m = tid0; m < M_TOT; m += stride) {
        uint4* d = (uint4*)(tc + (size_t)m * 64 + 32);
        d[0] = make_uint4(0, 0, 0, 0);
        d[1] = make_uint4(0, 0, 0, 0);
        d[2] = make_uint4(0, 0, 0, 0);
        d[3] = make_uint4(0, 0, 0, 0);
    }
}

// ---------------------------------------------------------------------------
// proj_mma: Tc[m][0..15]=hi, [16..31]=lo of In[m,:] @ Ah[16,:]^T via tensor
// cores. CTA: 128 thr / 4 warps, 64 rows; warp tile 16x16; 3-stage cp.async.
// Loads issued before compute (measured faster: 29.1 -> 25.8us).
// ---------------------------------------------------------------------------
__global__ __launch_bounds__(128)
void proj_mma_kernel(const __half* __restrict__ In, const __half* __restrict__ Ah,
                     __half* __restrict__ Tc, int Kd) {
    constexpr int A_BYTES = 64 * ROWSTRIDE * 2;   // 9216
    constexpr int B_BYTES = 16 * ROWSTRIDE * 2;   // 2304
    constexpr int STG = A_BYTES + B_BYTES;

    extern __shared__ char smem[];
    const uint32_t sb = smem_u32(smem);

    const int tid = threadIdx.x;
    const int lane = tid & 31;
    const int w = tid >> 5;
    const int m0 = blockIdx.x * 64;

    const uint32_t aoff = ((uint32_t)(w * 16 + (lane & 15)) * ROWSTRIDE + (lane >> 4) * 8) * 2;
    const uint32_t boff = ((uint32_t)(((lane >> 4) & 1) * 8 + (lane & 7)) * ROWSTRIDE +
                           ((lane >> 3) & 1) * 8) * 2;

    float acc[2][4] = {{0.f, 0.f, 0.f, 0.f}, {0.f, 0.f, 0.f, 0.f}};

    const int nchunks = Kd / BK;

    auto load_tile = [&](int stage, int c) {
        const uint32_t sA = sb + stage * STG;
        const uint32_t sB = sA + A_BYTES;
        const int kk = c * BK;
#pragma unroll
        for (int j = 0; j < 4; j++) {
            int u = j * 128 + tid;
            int row = u >> 3, grp = u & 7;
            CP_ASYNC16(sA + (uint32_t)(row * ROWSTRIDE + grp * 8) * 2,
                       In + (size_t)(m0 + row) * Kd + kk + grp * 8);
        }
        {
            int row = tid >> 3, grp = tid & 7;
            CP_ASYNC16(sB + (uint32_t)(row * ROWSTRIDE + grp * 8) * 2,
                       Ah + (size_t)row * Kd + kk + grp * 8);
        }
    };

    load_tile(0, 0);
    CP_COMMIT();
    if (nchunks > 1) load_tile(1, 1);
    CP_COMMIT();

    for (int t = 0; t < nchunks; t++) {
        CP_WAIT(1);
        __syncthreads();
        // issue next tile's loads BEFORE compute
        if (t + 2 < nchunks) load_tile((t + 2) % 3, t + 2);
        CP_COMMIT();

        const uint32_t sA = sb + (t % 3) * STG;
        const uint32_t sB = sA + A_BYTES;
#pragma unroll
        for (int s4 = 0; s4 < 4; s4++) {
            uint32_t af[4], bf[4];
            LDSM4(af, sA + aoff + s4 * 32);
            LDSM4(bf, sB + boff + s4 * 32);
            MMA16816H(acc[0], af, bf[0], bf[1]);
            MMA16816H(acc[1], af, bf[2], bf[3]);
        }
        __syncthreads();
    }

    // epilogue: warp covers rows m0+w*16..+16, cols 0..15
    const int rbase = m0 + w * 16 + (lane >> 2);
#pragma unroll
    for (int g = 0; g < 2; g++) {
        const int c = g * 8 + (lane & 3) * 2;
#pragma unroll
        for (int hh = 0; hh < 2; hh++) {
            const int gm = rbase + hh * 8;
            float v0 = acc[g][hh * 2 + 0];
            float v1 = acc[g][hh * 2 + 1];
            __half h0 = __float2half_rn(v0), h1 = __float2half_rn(v1);
            __half2 ph = __halves2half2(h0, h1);
            *(uint32_t*)(Tc + (size_t)gm * 64 + c) = *(uint32_t*)&ph;
            *(uint32_t*)(Tc + (size_t)gm * 64 + 16 + c) =
                pack2h(v0 - __half2float(h0), v1 - __half2float(h1));
        }
    }
}

// ---------------------------------------------------------------------------
// K-dim segments (single fp16 pass + LoRA tail)
// ---------------------------------------------------------------------------
struct Segs {
    const __half* a[2];
    const __half* b[2];
    int sa[2];
    int sb[2];
    int nchunks[2];
};

// ---------------------------------------------------------------------------
// fp16 mma.sync GEMM — exact R14 structure (single barrier per iteration,
// loads issued after the MMAs). Best measured config: 502us total.
// ---------------------------------------------------------------------------
template <int DO_GELU, int BNT>
__global__ __launch_bounds__(256, 2)
void fc_mma_kernel(Segs segs, int total_chunks,
                   const float* __restrict__ bias,
                   __half* __restrict__ Ch, float* __restrict__ Cf, int Nld) {
    constexpr int NJ = BNT / 32;
    constexpr int A_BYTES = BM * ROWSTRIDE * 2;
    constexpr int B_BYTES = BNT * ROWSTRIDE * 2;
    constexpr int STG_BYTES = A_BYTES + B_BYTES;

    extern __shared__ char smem[];
    const uint32_t smem_base = smem_u32(smem);

    const int tid = threadIdx.x;
    const int wid = tid >> 5;
    const int lane = tid & 31;
    const int wm = wid >> 1;
    const int wn = wid & 1;
    const int m0 = blockIdx.y * BM;
    const int n0 = blockIdx.x * BNT;

    int ls = 0, lc = 0;

    const uint32_t aoff = ((uint32_t)(wm * 32 + (lane & 15)) * ROWSTRIDE + (lane >> 4) * 8) * 2;
    const uint32_t boff = ((uint32_t)(wn * (BNT / 2) + ((lane >> 4) & 1) * 8 + (lane & 7)) * ROWSTRIDE +
                           ((lane >> 3) & 1) * 8) * 2;

    float acc[2][NJ * 2][4];
#pragma unroll
    for (int i = 0; i < 2; i++)
#pragma unroll
        for (int j = 0; j < NJ * 2; j++)
#pragma unroll
            for (int k = 0; k < 4; k++) acc[i][j][k] = 0.f;

    auto load_tile = [&](int stage) {
        const __half* Ap = segs.a[ls];
        const __half* Bp = segs.b[ls];
        const int stA = segs.sa[ls];
        const int stB = segs.sb[ls];
        const int kk = lc * BK;
        const uint32_t sA = smem_base + stage * STG_BYTES;
        const uint32_t sB = sA + A_BYTES;
#pragma unroll
        for (int j = 0; j < 4; j++) {
            int u = j * 256 + tid;
            int row = u >> 3, grp = u & 7;
            int gm = m0 + row;
            if (gm >= M_TOT) gm = M_TOT - 1;
            CP_ASYNC16(sA + (uint32_t)(row * ROWSTRIDE + grp * 8) * 2,
                       Ap + (size_t)gm * stA + kk + grp * 8);
        }
#pragma unroll
        for (int j = 0; j < BNT / 32; j++) {
            int u = j * 256 + tid;
            int row = u >> 3, grp = u & 7;
            CP_ASYNC16(sB + (uint32_t)(row * ROWSTRIDE + grp * 8) * 2,
                       Bp + (size_t)(n0 + row) * stB + kk + grp * 8);
        }
        if (++lc == segs.nchunks[ls]) { lc = 0; ++ls; }
    };

#pragma unroll
    for (int s = 0; s < STAGES - 1; s++) {
        load_tile(s);
        CP_COMMIT();
    }

    for (int t = 0; t < total_chunks; t++) {
        CP_WAIT(STAGES - 2);
        __syncthreads();

        const uint32_t sA = smem_base + (t % STAGES) * STG_BYTES;
        const uint32_t sB = sA + A_BYTES;

#pragma unroll
        for (int sub = 0; sub < 2; sub++) {
            const uint32_t ksub = (uint32_t)(sub * 32) * 2;
            uint32_t af[2][2][4];
#pragma unroll
            for (int mi = 0; mi < 2; mi++)
#pragma unroll
                for (int k = 0; k < 2; k++)
                    LDSM4(af[mi][k], sA + aoff + ksub + (uint32_t)(mi * 16 * ROWSTRIDE + k * 16) * 2);

#pragma unroll
            for (int nj = 0; nj < NJ; nj++) {
                uint32_t bf[2][4];
#pragma unroll
                for (int k = 0; k < 2; k++)
                    LDSM4(bf[k], sB + boff + ksub + (uint32_t)(nj * 16 * ROWSTRIDE + k * 16) * 2);
#pragma unroll
                for (int mi = 0; mi < 2; mi++)
#pragma unroll
                    for (int h = 0; h < 2; h++) {
                        MMA16816H(acc[mi][nj * 2 + h], af[mi][0], bf[0][h * 2], bf[0][h * 2 + 1]);
                        MMA16816H(acc[mi][nj * 2 + h], af[mi][1], bf[1][h * 2], bf[1][h * 2 + 1]);
                    }
            }
        }

        if (t + STAGES - 1 < total_chunks) load_tile((t + STAGES - 1) % STAGES);
        CP_COMMIT();
    }

    // ---- epilogue ----
#pragma unroll
    for (int mi = 0; mi < 2; mi++) {
        const int rbase = m0 + wm * 32 + mi * 16 + (lane >> 2);
#pragma unroll
        for (int ni = 0; ni < NJ * 2; ni++) {
            const int gn = n0 + wn * (BNT / 2) + ni * 8 + (lane & 3) * 2;
            const float b0 = __ldg(bias + gn);
            const float b1 = __ldg(bias + gn + 1);
#pragma unroll
            for (int h = 0; h < 2; h++) {
                const int gm = rbase + h * 8;
                if (gm >= M_TOT) continue;
                float v0 = acc[mi][ni][h * 2 + 0] + b0;
                float v1 = acc[mi][ni][h * 2 + 1] + b1;
                if (DO_GELU) {
                    v0 = 0.5f * v0 * (1.0f + erff(v0 * 0.70710678118654752f));
                    v1 = 0.5f * v1 * (1.0f + erff(v1 * 0.70710678118654752f));
                    *(uint32_t*)(Ch + (size_t)gm * Nld + gn) = pack2h(v0, v1);
                } else {
                    *(float2*)(Cf + (size_t)gm * Nld + gn) = make_float2(v0, v1);
                }
            }
        }
    }
}

// ---------------------------------------------------------------------------
// Launch sequence
// ---------------------------------------------------------------------------
extern "C" void kernel_launch(void* const* d_in, const int* in_sizes, int n_in,
                              void* d_out, int out_size) {
    const float* x  = (const float*)d_in[0];
    const float* W1 = (const float*)d_in[1];
    const float* b1 = (const float*)d_in[2];
    const float* A1 = (const float*)d_in[3];
    const float* B1 = (const float*)d_in[4];
    const float* W2 = (const float*)d_in[5];
    const float* b2 = (const float*)d_in[6];
    const float* A2 = (const float*)d_in[7];
    const float* B2 = (const float*)d_in[8];
    float* out = (float*)d_out;

    __half *xh, *w1h, *w2h, *hh, *tc, *bc1, *bc2, *a1h, *a2h;
    cudaGetSymbolAddress((void**)&xh,  g_x);
    cudaGetSymbolAddress((void**)&w1h, g_w1);
    cudaGetSymbolAddress((void**)&w2h, g_w2);
    cudaGetSymbolAddress((void**)&hh,  g_h);
    cudaGetSymbolAddress((void**)&tc,  g_tc);
    cudaGetSymbolAddress((void**)&bc1, g_bc1);
    cudaGetSymbolAddress((void**)&bc2, g_bc2);
    cudaGetSymbolAddress((void**)&a1h, g_a1h);
    cudaGetSymbolAddress((void**)&a2h, g_a2h);

    constexpr int SM1 = STAGES * (BM * ROWSTRIDE * 2 + 128 * ROWSTRIDE * 2);
    constexpr int SM2 = STAGES * (BM * ROWSTRIDE * 2 + 64 * ROWSTRIDE * 2);
    constexpr int SMP = 3 * (64 * ROWSTRIDE * 2 + 16 * ROWSTRIDE * 2);   // 34560
    cudaFuncSetAttribute((const void*)fc_mma_kernel<1, 128>,
                         cudaFuncAttributeMaxDynamicSharedMemorySize, SM1);
    cudaFuncSetAttribute((const void*)fc_mma_kernel<0, 64>,
                         cudaFuncAttributeMaxDynamicSharedMemorySize, SM2);
    cudaFuncSetAttribute((const void*)proj_mma_kernel,
                         cudaFuncAttributeMaxDynamicSharedMemorySize, SMP);

    prep_all_kernel<<<592, 256>>>(
        (const float4*)x, (uint2*)xh,
        (const float4*)W1, (uint2*)w1h,
        (const float4*)W2, (uint2*)w2h,
        B1, bc1, B2, bc2,
        (const float4*)A1, (uint2*)a1h,
        (const float4*)A2, (uint2*)a2h, tc);

    proj_mma_kernel<<<M_TOT / 64, 128, SMP>>>(xh, a1h, tc, D_DIM);

    {
        Segs s;
        s.a[0] = xh; s.b[0] = w1h; s.sa[0] = D_DIM; s.sb[0] = D_DIM; s.nchunks[0] = D_DIM / BK;
        s.a[1] = tc; s.b[1] = bc1; s.sa[1] = 64;    s.sb[1] = 64;    s.nchunks[1] = 1;
        int total = D_DIM / BK + 1;  // 13
        dim3 grid(H_DIM / 128, (M_TOT + BM - 1) / BM);
        fc_mma_kernel<1, 128><<<grid, 256, SM1>>>(s, total, b1, hh, nullptr, H_DIM);
    }

    proj_mma_kernel<<<M_TOT / 64, 128, SMP>>>(hh, a2h, tc, H_DIM);

    {
        Segs s;
        s.a[0] = hh; s.b[0] = w2h; s.sa[0] = H_DIM; s.sb[0] = H_DIM; s.nchunks[0] = H_DIM / BK;
        s.a[1] = tc; s.b[1] = bc2; s.sa[1] = 64;    s.sb[1] = 64;    s.nchunks[1] = 1;
        int total = H_DIM / BK + 1;  // 49
        dim3 grid(D_DIM / 64, (M_TOT + BM - 1) / BM);
        fc_mma_kernel<0, 64><<<grid, 256, SM2>>>(s, total, b2, nullptr, out, D_DIM);
    }
}